// round 4
// baseline (speedup 1.0000x reference)
#include <cuda_runtime.h>
#include <stdint.h>

#define BB   16
#define CC   512
#define NN   1024
#define HH   8
#define DD   64
#define HIDC 2048

// ---------------- scratch (static __device__ globals; no allocations) --------
__device__ float          g_Y [(size_t)BB*HIDC*NN];   // GEMM output scratch (max size: fc1)
__device__ float          g_X1[(size_t)BB*CC*NN];     // residual-1 (x + proj spikes)
__device__ unsigned char  g_Qb[(size_t)BB*CC*NN];
__device__ unsigned char  g_Kb[(size_t)BB*CC*NN];
__device__ unsigned char  g_Vb[(size_t)BB*CC*NN];
__device__ unsigned char  g_Ab[(size_t)BB*CC*NN];     // post-attention spikes
__device__ unsigned char  g_H1[(size_t)BB*HIDC*NN];   // fc1 spikes
__device__ float          g_mean[HIDC];
__device__ float          g_rstd[HIDC];

// ---------------- tiled GEMM: Y[b,o,n] = sum_c W[o,c] * X[b,c,n] (+bias) -----
__device__ __forceinline__ void load4f(float* dst, const float* src) {
    float4 v = *reinterpret_cast<const float4*>(src);
    dst[0]=v.x; dst[1]=v.y; dst[2]=v.z; dst[3]=v.w;
}
__device__ __forceinline__ void load4f(float* dst, const unsigned char* src) {
    uchar4 v = *reinterpret_cast<const uchar4*>(src);
    dst[0]=(float)v.x; dst[1]=(float)v.y; dst[2]=(float)v.z; dst[3]=(float)v.w;
}

template<typename T>
__global__ __launch_bounds__(256) void gemm_kernel(
    const float* __restrict__ W, const T* __restrict__ X,
    const float* __restrict__ bias, float* __restrict__ Y, int O, int K)
{
    const int N = NN;
    int b  = blockIdx.z;
    int o0 = blockIdx.y * 64;
    int n0 = blockIdx.x * 64;
    const T* Xb = X + (size_t)b * K * N;
    float*   Yb = Y + (size_t)b * O * N;

    __shared__ float As[16][64];   // [kk][o]
    __shared__ float Bs[16][68];   // [kk][n] (+pad)

    int tid = threadIdx.x;
    int ty = tid >> 4, tx = tid & 15;

    float acc[4][4];
    #pragma unroll
    for (int i=0;i<4;i++)
        #pragma unroll
        for (int j=0;j<4;j++) acc[i][j]=0.f;

    int wl_o = tid >> 2;          // 0..63
    int wl_k = (tid & 3) * 4;     // 0,4,8,12
    int xl_k = tid >> 4;          // 0..15
    int xl_n = (tid & 15) * 4;    // 0..60

    for (int k0 = 0; k0 < K; k0 += 16) {
        float4 wv = *reinterpret_cast<const float4*>(W + (size_t)(o0+wl_o)*K + k0 + wl_k);
        As[wl_k+0][wl_o]=wv.x; As[wl_k+1][wl_o]=wv.y;
        As[wl_k+2][wl_o]=wv.z; As[wl_k+3][wl_o]=wv.w;
        load4f(&Bs[xl_k][xl_n], Xb + (size_t)(k0+xl_k)*N + n0 + xl_n);
        __syncthreads();
        #pragma unroll
        for (int kk=0; kk<16; kk++) {
            float a[4], bv[4];
            #pragma unroll
            for (int i=0;i<4;i++) a[i]  = As[kk][ty + 16*i];
            #pragma unroll
            for (int j=0;j<4;j++) bv[j] = Bs[kk][tx + 16*j];
            #pragma unroll
            for (int i=0;i<4;i++)
                #pragma unroll
                for (int j=0;j<4;j++) acc[i][j] = fmaf(a[i], bv[j], acc[i][j]);
        }
        __syncthreads();
    }
    #pragma unroll
    for (int i=0;i<4;i++) {
        int o = o0 + ty + 16*i;
        float bvv = bias ? bias[o] : 0.f;
        #pragma unroll
        for (int j=0;j<4;j++)
            Yb[(size_t)o*NN + n0 + tx + 16*j] = acc[i][j] + bvv;
    }
}

// ---------------- per-channel batch stats over (B, N) ------------------------
__global__ __launch_bounds__(256) void stats_kernel(
    const float* __restrict__ Y, int O, float* __restrict__ mean, float* __restrict__ rstd)
{
    int o = blockIdx.x;
    int tid = threadIdx.x;
    float s = 0.f, sq = 0.f;
    for (int b = 0; b < BB; b++) {
        const float* p = Y + (size_t)b*O*NN + (size_t)o*NN;
        for (int n = tid; n < NN; n += 256) { float v = p[n]; s += v; sq += v*v; }
    }
    __shared__ float sh0[256], sh1[256];
    sh0[tid]=s; sh1[tid]=sq; __syncthreads();
    for (int st=128; st>0; st>>=1) {
        if (tid < st) { sh0[tid]+=sh0[tid+st]; sh1[tid]+=sh1[tid+st]; }
        __syncthreads();
    }
    if (tid == 0) {
        const float cnt = (float)(BB*NN);
        float m = sh0[0]/cnt;
        float v = sh1[0]/cnt - m*m;
        mean[o] = m;
        rstd[o] = rsqrtf(v + 1e-5f);
    }
}

// ---------------- binarize variants: spike = (bn(y) >= TAU*THRESH = 2) -------
__global__ __launch_bounds__(256) void bin_u8_kernel(
    const float* __restrict__ Y, const float* __restrict__ mean, const float* __restrict__ rstd,
    const float* __restrict__ g, const float* __restrict__ bb,
    unsigned char* __restrict__ out, int O)
{
    size_t i = (size_t)blockIdx.x * 256 + threadIdx.x;
    int o = (int)((i / NN) % O);
    float z = (Y[i] - mean[o]) * rstd[o] * g[o] + bb[o];
    out[i] = (z >= 2.0f) ? 1 : 0;
}

__global__ __launch_bounds__(256) void bin_resid_kernel(
    const float* __restrict__ Y, const float* __restrict__ mean, const float* __restrict__ rstd,
    const float* __restrict__ g, const float* __restrict__ bb,
    const float* __restrict__ x, float* __restrict__ X1, int O)
{
    size_t i = (size_t)blockIdx.x * 256 + threadIdx.x;
    int o = (int)((i / NN) % O);
    float z = (Y[i] - mean[o]) * rstd[o] * g[o] + bb[o];
    X1[i] = x[i] + ((z >= 2.0f) ? 1.0f : 0.0f);
}

__global__ __launch_bounds__(256) void bin_final_kernel(
    const float* __restrict__ Y, const float* __restrict__ mean, const float* __restrict__ rstd,
    const float* __restrict__ g, const float* __restrict__ bb,
    const float* __restrict__ X1, float* __restrict__ out, int O)
{
    size_t i = (size_t)blockIdx.x * 256 + threadIdx.x;
    int o = (int)((i / NN) % O);
    float z = (Y[i] - mean[o]) * rstd[o] * g[o] + bb[o];
    out[i] = X1[i] + ((z >= 2.0f) ? 1.0f : 0.0f);
}

// ---------------- fused spiking attention: A = lif(Q (K^T V) * 0.25) --------
// Binary Q,K,V => M = K^T V is an integer count matrix [64,64];
// lif(0.25*s / 2 - 1 >= 0) <=> s >= 8 (exact integer compare).
__global__ __launch_bounds__(256) void attn_kernel(
    const unsigned char* __restrict__ Q, const unsigned char* __restrict__ K,
    const unsigned char* __restrict__ V, unsigned char* __restrict__ A)
{
    int b = blockIdx.x >> 3;
    int h = blockIdx.x & 7;
    size_t base = (size_t)b*CC*NN + (size_t)h*DD*NN;

    __shared__ unsigned char ksh[64][132];  // padded rows: bank-conflict-free
    __shared__ unsigned char vsh[64][132];
    __shared__ int Msh[64][64];

    int tid = threadIdx.x;

    // ---- Phase 1: M[d][e] = sum_n K[d,n] * V[e,n] ----
    int d  = tid >> 2;
    int e0 = (tid & 3) * 16;
    int acc[16];
    #pragma unroll
    for (int e=0;e<16;e++) acc[e]=0;

    for (int n0 = 0; n0 < NN; n0 += 128) {
        for (int w = tid; w < 2048; w += 256) {
            int r = w >> 5, c4 = w & 31;
            *reinterpret_cast<uint32_t*>(&ksh[r][c4*4]) =
                *reinterpret_cast<const uint32_t*>(K + base + (size_t)r*NN + n0 + c4*4);
            *reinterpret_cast<uint32_t*>(&vsh[r][c4*4]) =
                *reinterpret_cast<const uint32_t*>(V + base + (size_t)r*NN + n0 + c4*4);
        }
        __syncthreads();
        for (int j = 0; j < 128; j++) {
            if (ksh[d][j]) {           // ~2-5% spike density: mostly skipped
                #pragma unroll
                for (int e=0;e<16;e++) acc[e] += (int)vsh[e0+e][j];
            }
        }
        __syncthreads();
    }
    #pragma unroll
    for (int e=0;e<16;e++) Msh[d][e0+e] = acc[e];
    __syncthreads();

    // ---- Phase 2: s[n][e] = sum_d Q[d,n] * M[d][e]; spike = (s >= 8) ----
    int nl = tid & 127;
    int er = (tid >> 7) * 32;
    for (int n0 = 0; n0 < NN; n0 += 128) {
        for (int w = tid; w < 2048; w += 256) {   // reuse ksh as Q tile
            int r = w >> 5, c4 = w & 31;
            *reinterpret_cast<uint32_t*>(&ksh[r][c4*4]) =
                *reinterpret_cast<const uint32_t*>(Q + base + (size_t)r*NN + n0 + c4*4);
        }
        __syncthreads();
        int s[32];
        #pragma unroll
        for (int e=0;e<32;e++) s[e]=0;
        for (int dd = 0; dd < 64; dd++) {
            if (ksh[dd][nl]) {
                #pragma unroll
                for (int e=0;e<32;e++) s[e] += Msh[dd][er+e];
            }
        }
        #pragma unroll
        for (int e=0;e<32;e++)
            A[base + (size_t)(er+e)*NN + n0 + nl] = (s[e] >= 8) ? 1 : 0;
        __syncthreads();
    }
}

// ---------------- launch -----------------------------------------------------
extern "C" void kernel_launch(void* const* d_in, const int* in_sizes, int n_in,
                              void* d_out, int out_size)
{
    const float* x        = (const float*)d_in[0];
    const float* q_w      = (const float*)d_in[1];
    const float* q_g      = (const float*)d_in[2];
    const float* q_b      = (const float*)d_in[3];
    const float* k_w      = (const float*)d_in[4];
    const float* k_g      = (const float*)d_in[5];
    const float* k_b      = (const float*)d_in[6];
    const float* v_w      = (const float*)d_in[7];
    const float* v_g      = (const float*)d_in[8];
    const float* v_b      = (const float*)d_in[9];
    const float* proj_w   = (const float*)d_in[10];
    const float* proj_bias= (const float*)d_in[11];
    const float* proj_g   = (const float*)d_in[12];
    const float* proj_b   = (const float*)d_in[13];
    const float* fc1_w    = (const float*)d_in[14];
    const float* fc1_bias = (const float*)d_in[15];
    const float* fc1_g    = (const float*)d_in[16];
    const float* fc1_b    = (const float*)d_in[17];
    const float* fc2_w    = (const float*)d_in[18];
    const float* fc2_bias = (const float*)d_in[19];
    const float* fc2_g    = (const float*)d_in[20];
    const float* fc2_b    = (const float*)d_in[21];
    float* out = (float*)d_out;

    float *Y, *X1, *mean, *rstd;
    unsigned char *Qb, *Kb, *Vb, *Ab, *H1;
    cudaGetSymbolAddress((void**)&Y,    g_Y);
    cudaGetSymbolAddress((void**)&X1,   g_X1);
    cudaGetSymbolAddress((void**)&mean, g_mean);
    cudaGetSymbolAddress((void**)&rstd, g_rstd);
    cudaGetSymbolAddress((void**)&Qb,   g_Qb);
    cudaGetSymbolAddress((void**)&Kb,   g_Kb);
    cudaGetSymbolAddress((void**)&Vb,   g_Vb);
    cudaGetSymbolAddress((void**)&Ab,   g_Ab);
    cudaGetSymbolAddress((void**)&H1,   g_H1);

    dim3 blk(256);
    dim3 g512 (NN/64, CC/64,   BB);   // (16, 8, 16)
    dim3 g2048(NN/64, HIDC/64, BB);   // (16, 32, 16)
    int gbC = (int)(((size_t)BB*CC*NN)   / 256);   // 32768
    int gbH = (int)(((size_t)BB*HIDC*NN) / 256);   // 131072

    // Q / K / V branches: conv1x1 -> BN stats -> binarize
    gemm_kernel<float><<<g512, blk>>>(q_w, x, nullptr, Y, CC, CC);
    stats_kernel<<<CC, 256>>>(Y, CC, mean, rstd);
    bin_u8_kernel<<<gbC, 256>>>(Y, mean, rstd, q_g, q_b, Qb, CC);

    gemm_kernel<float><<<g512, blk>>>(k_w, x, nullptr, Y, CC, CC);
    stats_kernel<<<CC, 256>>>(Y, CC, mean, rstd);
    bin_u8_kernel<<<gbC, 256>>>(Y, mean, rstd, k_g, k_b, Kb, CC);

    gemm_kernel<float><<<g512, blk>>>(v_w, x, nullptr, Y, CC, CC);
    stats_kernel<<<CC, 256>>>(Y, CC, mean, rstd);
    bin_u8_kernel<<<gbC, 256>>>(Y, mean, rstd, v_g, v_b, Vb, CC);

    // Fused spiking attention via Q(K^T V): [64x64] inner matrix per head
    attn_kernel<<<BB*HH, 256>>>(Qb, Kb, Vb, Ab);

    // proj -> BN -> spike -> residual 1 (X1 = x + spike)
    gemm_kernel<unsigned char><<<g512, blk>>>(proj_w, Ab, proj_bias, Y, CC, CC);
    stats_kernel<<<CC, 256>>>(Y, CC, mean, rstd);
    bin_resid_kernel<<<gbC, 256>>>(Y, mean, rstd, proj_g, proj_b, x, X1, CC);

    // fc1 -> BN -> spike
    gemm_kernel<float><<<g2048, blk>>>(fc1_w, X1, fc1_bias, Y, HIDC, CC);
    stats_kernel<<<HIDC, 256>>>(Y, HIDC, mean, rstd);
    bin_u8_kernel<<<gbH, 256>>>(Y, mean, rstd, fc1_g, fc1_b, H1, HIDC);

    // fc2 -> BN -> spike -> residual 2 (out = X1 + spike)
    gemm_kernel<unsigned char><<<g512, blk>>>(fc2_w, H1, fc2_bias, Y, CC, HIDC);
    stats_kernel<<<CC, 256>>>(Y, CC, mean, rstd);
    bin_final_kernel<<<gbC, 256>>>(Y, mean, rstd, fc2_g, fc2_b, X1, out, CC);
}

// round 5
// speedup vs baseline: 2.1164x; 2.1164x over previous
#include <cuda_runtime.h>
#include <stdint.h>

#define BB   16
#define CC   512
#define NN   1024
#define HH   8
#define DD   64
#define HIDC 2048

// ---------------- scratch (static __device__ globals; no allocations) --------
__device__ float          g_Y [(size_t)BB*HIDC*NN];     // GEMM output scratch (max: fc1)
__device__ float          g_X1[(size_t)BB*CC*NN];       // residual-1 (x + proj spikes)
__device__ unsigned char  g_Qb[(size_t)BB*CC*NN];
__device__ unsigned char  g_Kb[(size_t)BB*CC*NN];
__device__ unsigned char  g_Vb[(size_t)BB*CC*NN];
__device__ uint32_t       g_Abits [(size_t)BB*NN*(CC/32)];     // attn spikes, bit-packed [b][n][c/32]
__device__ uint32_t       g_H1bits[(size_t)BB*NN*(HIDC/32)];   // fc1 spikes,  bit-packed [b][n][c/32]
__device__ float          g_Wt[(size_t)HIDC*CC];        // transposed weights [K][O]
__device__ float          g_mean[HIDC];
__device__ float          g_rstd[HIDC];

// ---------------- dense GEMM: Y[b,o,n] = sum_c W[o,c] * X[b,c,n] (+bias) -----
// 128x128 block tile, Ktile=16, 256 threads, 8x8 per-thread, double-buffered.
__global__ __launch_bounds__(256, 2) void gemm128(
    const float* __restrict__ W, const float* __restrict__ X,
    const float* __restrict__ bias, float* __restrict__ Y, int O, int K)
{
    __shared__ float As[2][16][128];   // [buf][k][o]
    __shared__ float Bs[2][16][128];   // [buf][k][n]

    int b  = blockIdx.z;
    int o0 = blockIdx.y * 128;
    int n0 = blockIdx.x * 128;
    const float* Xb = X + (size_t)b * K * NN;
    float*       Yb = Y + (size_t)b * O * NN;

    int tid  = threadIdx.x;
    int wrow = tid >> 1;           // 0..127  (o within tile)
    int wk   = (tid & 1) * 8;      // 0 or 8  (k)
    int xrow = tid >> 4;           // 0..15   (k)
    int xcol = (tid & 15) * 8;     // 0..120  (n)

    const float* Wp = W  + (size_t)(o0 + wrow) * K + wk;
    const float* Xp = Xb + (size_t)xrow * NN + n0 + xcol;

    float wr[8], xr[8];
    {
        float4 a = *(const float4*)(Wp);
        float4 c = *(const float4*)(Wp + 4);
        wr[0]=a.x; wr[1]=a.y; wr[2]=a.z; wr[3]=a.w; wr[4]=c.x; wr[5]=c.y; wr[6]=c.z; wr[7]=c.w;
        float4 d = *(const float4*)(Xp);
        float4 e = *(const float4*)(Xp + 4);
        xr[0]=d.x; xr[1]=d.y; xr[2]=d.z; xr[3]=d.w; xr[4]=e.x; xr[5]=e.y; xr[6]=e.z; xr[7]=e.w;
    }
    int buf = 0;
    #pragma unroll
    for (int i = 0; i < 8; i++) As[0][wk + i][wrow] = wr[i];
    *(float4*)&Bs[0][xrow][xcol]     = *(float4*)&xr[0];
    *(float4*)&Bs[0][xrow][xcol + 4] = *(float4*)&xr[4];
    __syncthreads();

    float acc[8][8];
    #pragma unroll
    for (int i = 0; i < 8; i++)
        #pragma unroll
        for (int j = 0; j < 8; j++) acc[i][j] = 0.f;

    int ty = tid >> 4, tx = tid & 15;

    for (int k0 = 16; k0 <= K; k0 += 16) {
        if (k0 < K) {
            const float* wp = Wp + k0;
            float4 a = *(const float4*)(wp);
            float4 c = *(const float4*)(wp + 4);
            wr[0]=a.x; wr[1]=a.y; wr[2]=a.z; wr[3]=a.w; wr[4]=c.x; wr[5]=c.y; wr[6]=c.z; wr[7]=c.w;
            const float* xp = Xp + (size_t)k0 * NN;
            float4 d = *(const float4*)(xp);
            float4 e = *(const float4*)(xp + 4);
            xr[0]=d.x; xr[1]=d.y; xr[2]=d.z; xr[3]=d.w; xr[4]=e.x; xr[5]=e.y; xr[6]=e.z; xr[7]=e.w;
        }
        #pragma unroll
        for (int kk = 0; kk < 16; kk++) {
            float4 a0 = *(float4*)&As[buf][kk][ty * 4];
            float4 a1 = *(float4*)&As[buf][kk][64 + ty * 4];
            float4 b0 = *(float4*)&Bs[buf][kk][tx * 4];
            float4 b1 = *(float4*)&Bs[buf][kk][64 + tx * 4];
            float av[8] = {a0.x,a0.y,a0.z,a0.w,a1.x,a1.y,a1.z,a1.w};
            float bv[8] = {b0.x,b0.y,b0.z,b0.w,b1.x,b1.y,b1.z,b1.w};
            #pragma unroll
            for (int i = 0; i < 8; i++)
                #pragma unroll
                for (int j = 0; j < 8; j++)
                    acc[i][j] = fmaf(av[i], bv[j], acc[i][j]);
        }
        if (k0 < K) {
            buf ^= 1;
            #pragma unroll
            for (int i = 0; i < 8; i++) As[buf][wk + i][wrow] = wr[i];
            *(float4*)&Bs[buf][xrow][xcol]     = *(float4*)&xr[0];
            *(float4*)&Bs[buf][xrow][xcol + 4] = *(float4*)&xr[4];
            __syncthreads();
        }
    }

    #pragma unroll
    for (int i = 0; i < 8; i++) {
        int o = o0 + ((i < 4) ? (ty * 4 + i) : (64 + ty * 4 + (i - 4)));
        float bvv = bias ? bias[o] : 0.f;
        float4 r0 = {acc[i][0]+bvv, acc[i][1]+bvv, acc[i][2]+bvv, acc[i][3]+bvv};
        float4 r1 = {acc[i][4]+bvv, acc[i][5]+bvv, acc[i][6]+bvv, acc[i][7]+bvv};
        *(float4*)&Yb[(size_t)o * NN + n0 + tx * 4]      = r0;
        *(float4*)&Yb[(size_t)o * NN + n0 + 64 + tx * 4] = r1;
    }
}

// ---------------- weight transpose: Wt[k][o] = W[o][k] -----------------------
__global__ __launch_bounds__(256) void transpose_w(
    const float* __restrict__ W, float* __restrict__ Wt, int O, int K)
{
    __shared__ float t[32][33];
    int k0 = blockIdx.x * 32, o0 = blockIdx.y * 32;
    int x = threadIdx.x & 31, y = threadIdx.x >> 5;   // 32 x 8
    #pragma unroll
    for (int i = 0; i < 32; i += 8)
        t[y + i][x] = W[(size_t)(o0 + y + i) * K + k0 + x];
    __syncthreads();
    #pragma unroll
    for (int i = 0; i < 32; i += 8)
        Wt[(size_t)(k0 + y + i) * O + o0 + x] = t[x][y + i];
}

// ---------------- sparse binary GEMM: Y = bias + sum_{c: Xbits[b,n,c]=1} Wt[c,:] ----
// One block per (b,n) column. Ordered active list (deterministic sum order).
__global__ __launch_bounds__(128) void sparse_gemm(
    const float* __restrict__ Wt,        // [K][512]
    const uint32_t* __restrict__ Xbits,  // [B][N][K/32]
    const float* __restrict__ bias,
    float* __restrict__ Y, int K)        // O fixed = 512
{
    const int O = CC;
    int n = blockIdx.x & (NN - 1);
    int b = blockIdx.x >> 10;
    int tid = threadIdx.x;
    int W32 = K >> 5;

    __shared__ uint16_t act[HIDC];
    __shared__ int s_cnt;

    const uint32_t* colbits = Xbits + ((size_t)b * NN + n) * W32;

    if (tid < 32) {
        int cnt = 0;
        for (int w0 = 0; w0 < W32; w0 += 32) {
            uint32_t bits = (w0 + tid < W32) ? colbits[w0 + tid] : 0u;
            int pc = __popc(bits);
            int sc = pc;
            #pragma unroll
            for (int d = 1; d < 32; d <<= 1) {
                int t = __shfl_up_sync(0xffffffffu, sc, d);
                if (tid >= d) sc += t;
            }
            int off = cnt + sc - pc;
            int total = __shfl_sync(0xffffffffu, sc, 31);
            int base_c = (w0 + tid) * 32;
            while (bits) {
                int c = __ffs(bits) - 1;
                act[off++] = (uint16_t)(base_c + c);
                bits &= bits - 1;
            }
            cnt += total;
        }
        if (tid == 0) s_cnt = cnt;
    }
    __syncthreads();
    int cnt = s_cnt;

    int o = tid * 4;   // 128 threads x 4 = 512 outputs
    float4 acc;
    if (bias) acc = *(const float4*)&bias[o];
    else      acc = make_float4(0.f, 0.f, 0.f, 0.f);

    int i = 0;
    for (; i + 1 < cnt; i += 2) {
        float4 p0 = *(const float4*)&Wt[(size_t)act[i]     * O + o];
        float4 p1 = *(const float4*)&Wt[(size_t)act[i + 1] * O + o];
        acc.x += p0.x; acc.y += p0.y; acc.z += p0.z; acc.w += p0.w;
        acc.x += p1.x; acc.y += p1.y; acc.z += p1.z; acc.w += p1.w;
    }
    if (i < cnt) {
        float4 p0 = *(const float4*)&Wt[(size_t)act[i] * O + o];
        acc.x += p0.x; acc.y += p0.y; acc.z += p0.z; acc.w += p0.w;
    }

    float* Yc = Y + (size_t)b * O * NN + n;
    Yc[(size_t)(o + 0) * NN] = acc.x;
    Yc[(size_t)(o + 1) * NN] = acc.y;
    Yc[(size_t)(o + 2) * NN] = acc.z;
    Yc[(size_t)(o + 3) * NN] = acc.w;
}

// ---------------- per-channel batch stats over (B, N) ------------------------
__global__ __launch_bounds__(256) void stats_kernel(
    const float* __restrict__ Y, int O, float* __restrict__ mean, float* __restrict__ rstd)
{
    int o = blockIdx.x;
    int tid = threadIdx.x;
    float s = 0.f, sq = 0.f;
    for (int b = 0; b < BB; b++) {
        const float* p = Y + (size_t)b*O*NN + (size_t)o*NN;
        for (int n = tid; n < NN; n += 256) { float v = p[n]; s += v; sq += v*v; }
    }
    __shared__ float sh0[256], sh1[256];
    sh0[tid]=s; sh1[tid]=sq; __syncthreads();
    for (int st=128; st>0; st>>=1) {
        if (tid < st) { sh0[tid]+=sh0[tid+st]; sh1[tid]+=sh1[tid+st]; }
        __syncthreads();
    }
    if (tid == 0) {
        const float cnt = (float)(BB*NN);
        float m = sh0[0]/cnt;
        float v = sh1[0]/cnt - m*m;
        mean[o] = m;
        rstd[o] = rsqrtf(v + 1e-5f);
    }
}

// ---------------- binarize variants: spike = (bn(y) >= 2) --------------------
__global__ __launch_bounds__(256) void bin_u8_kernel(
    const float* __restrict__ Y, const float* __restrict__ mean, const float* __restrict__ rstd,
    const float* __restrict__ g, const float* __restrict__ bb,
    unsigned char* __restrict__ out, int O)
{
    size_t i = (size_t)blockIdx.x * 256 + threadIdx.x;
    int o = (int)((i / NN) % O);
    float z = (Y[i] - mean[o]) * rstd[o] * g[o] + bb[o];
    out[i] = (z >= 2.0f) ? 1 : 0;
}

__global__ __launch_bounds__(256) void bin_resid_kernel(
    const float* __restrict__ Y, const float* __restrict__ mean, const float* __restrict__ rstd,
    const float* __restrict__ g, const float* __restrict__ bb,
    const float* __restrict__ x, float* __restrict__ X1, int O)
{
    size_t i = (size_t)blockIdx.x * 256 + threadIdx.x;
    int o = (int)((i / NN) % O);
    float z = (Y[i] - mean[o]) * rstd[o] * g[o] + bb[o];
    X1[i] = x[i] + ((z >= 2.0f) ? 1.0f : 0.0f);
}

__global__ __launch_bounds__(256) void bin_final_kernel(
    const float* __restrict__ Y, const float* __restrict__ mean, const float* __restrict__ rstd,
    const float* __restrict__ g, const float* __restrict__ bb,
    const float* __restrict__ X1, float* __restrict__ out, int O)
{
    size_t i = (size_t)blockIdx.x * 256 + threadIdx.x;
    int o = (int)((i / NN) % O);
    float z = (Y[i] - mean[o]) * rstd[o] * g[o] + bb[o];
    out[i] = X1[i] + ((z >= 2.0f) ? 1.0f : 0.0f);
}

// fc1 binarize + bit-pack: one warp per (b, c-word, n-block-of-32); lane = n.
__global__ __launch_bounds__(256) void bin_pack_kernel(
    const float* __restrict__ Y, const float* __restrict__ mean, const float* __restrict__ rstd,
    const float* __restrict__ g, const float* __restrict__ bb,
    uint32_t* __restrict__ Xbits)   // [B][N][HIDC/32]
{
    const int O = HIDC, W32 = HIDC / 32;
    int gw   = (blockIdx.x * blockDim.x + threadIdx.x) >> 5;
    int lane = threadIdx.x & 31;
    int nblk = gw & 31;                // N/32 = 32
    int w    = (gw >> 5) & (W32 - 1);  // 64 words
    int b    = gw >> 11;
    int n    = nblk * 32 + lane;

    uint32_t m = 0;
    #pragma unroll 8
    for (int e = 0; e < 32; e++) {
        int o = w * 32 + e;
        float z = (Y[((size_t)b * O + o) * NN + n] - mean[o]) * rstd[o] * g[o] + bb[o];
        m |= (z >= 2.0f) ? (1u << e) : 0u;
    }
    Xbits[((size_t)b * NN + n) * W32 + w] = m;
}

// ---------------- fused spiking attention: A = lif(Q (K^T V) * 0.25) --------
// Binary Q,K,V => M = K^T V integer [64,64]; lif(0.25*s/2 - 1 >= 0) <=> s >= 8.
// Output written bit-packed: Abits[b][n][c/32].
__global__ __launch_bounds__(256) void attn_kernel(
    const unsigned char* __restrict__ Q, const unsigned char* __restrict__ K,
    const unsigned char* __restrict__ V, uint32_t* __restrict__ Abits)
{
    int b = blockIdx.x >> 3;
    int h = blockIdx.x & 7;
    size_t base = (size_t)b*CC*NN + (size_t)h*DD*NN;

    __shared__ unsigned char ksh[64][132];
    __shared__ unsigned char vsh[64][132];
    __shared__ int Msh[64][64];

    int tid = threadIdx.x;

    // ---- Phase 1: M[d][e] = sum_n K[d,n] * V[e,n] ----
    int d  = tid >> 2;
    int e0 = (tid & 3) * 16;
    int acc[16];
    #pragma unroll
    for (int e=0;e<16;e++) acc[e]=0;

    for (int n0 = 0; n0 < NN; n0 += 128) {
        for (int w = tid; w < 2048; w += 256) {
            int r = w >> 5, c4 = w & 31;
            *reinterpret_cast<uint32_t*>(&ksh[r][c4*4]) =
                *reinterpret_cast<const uint32_t*>(K + base + (size_t)r*NN + n0 + c4*4);
            *reinterpret_cast<uint32_t*>(&vsh[r][c4*4]) =
                *reinterpret_cast<const uint32_t*>(V + base + (size_t)r*NN + n0 + c4*4);
        }
        __syncthreads();
        for (int j = 0; j < 128; j++) {
            if (ksh[d][j]) {
                #pragma unroll
                for (int e=0;e<16;e++) acc[e] += (int)vsh[e0+e][j];
            }
        }
        __syncthreads();
    }
    #pragma unroll
    for (int e=0;e<16;e++) Msh[d][e0+e] = acc[e];
    __syncthreads();

    // ---- Phase 2: s[n][e] = sum_d Q[d,n]*M[d][e]; bit = (s >= 8) ----
    int nl = tid & 127;
    int er = (tid >> 7) * 32;
    for (int n0 = 0; n0 < NN; n0 += 128) {
        for (int w = tid; w < 2048; w += 256) {   // reuse ksh as Q tile
            int r = w >> 5, c4 = w & 31;
            *reinterpret_cast<uint32_t*>(&ksh[r][c4*4]) =
                *reinterpret_cast<const uint32_t*>(Q + base + (size_t)r*NN + n0 + c4*4);
        }
        __syncthreads();
        int s[32];
        #pragma unroll
        for (int e=0;e<32;e++) s[e]=0;
        for (int dd = 0; dd < 64; dd++) {
            if (ksh[dd][nl]) {
                #pragma unroll
                for (int e=0;e<32;e++) s[e] += Msh[dd][er+e];
            }
        }
        uint32_t m = 0;
        #pragma unroll
        for (int e=0;e<32;e++) m |= (s[e] >= 8) ? (1u << e) : 0u;
        // channel word: c = h*64 + er + e  ->  word = h*2 + er/32, bit = e
        Abits[((size_t)b*NN + n0 + nl) * (CC/32) + h*2 + (er >> 5)] = m;
        __syncthreads();
    }
}

// ---------------- launch -----------------------------------------------------
extern "C" void kernel_launch(void* const* d_in, const int* in_sizes, int n_in,
                              void* d_out, int out_size)
{
    const float* x        = (const float*)d_in[0];
    const float* q_w      = (const float*)d_in[1];
    const float* q_g      = (const float*)d_in[2];
    const float* q_b      = (const float*)d_in[3];
    const float* k_w      = (const float*)d_in[4];
    const float* k_g      = (const float*)d_in[5];
    const float* k_b      = (const float*)d_in[6];
    const float* v_w      = (const float*)d_in[7];
    const float* v_g      = (const float*)d_in[8];
    const float* v_b      = (const float*)d_in[9];
    const float* proj_w   = (const float*)d_in[10];
    const float* proj_bias= (const float*)d_in[11];
    const float* proj_g   = (const float*)d_in[12];
    const float* proj_b   = (const float*)d_in[13];
    const float* fc1_w    = (const float*)d_in[14];
    const float* fc1_bias = (const float*)d_in[15];
    const float* fc1_g    = (const float*)d_in[16];
    const float* fc1_b    = (const float*)d_in[17];
    const float* fc2_w    = (const float*)d_in[18];
    const float* fc2_bias = (const float*)d_in[19];
    const float* fc2_g    = (const float*)d_in[20];
    const float* fc2_b    = (const float*)d_in[21];
    float* out = (float*)d_out;

    float *Y, *X1, *Wt, *mean, *rstd;
    unsigned char *Qb, *Kb, *Vb;
    uint32_t *Abits, *H1bits;
    cudaGetSymbolAddress((void**)&Y,      g_Y);
    cudaGetSymbolAddress((void**)&X1,     g_X1);
    cudaGetSymbolAddress((void**)&Wt,     g_Wt);
    cudaGetSymbolAddress((void**)&mean,   g_mean);
    cudaGetSymbolAddress((void**)&rstd,   g_rstd);
    cudaGetSymbolAddress((void**)&Qb,     g_Qb);
    cudaGetSymbolAddress((void**)&Kb,     g_Kb);
    cudaGetSymbolAddress((void**)&Vb,     g_Vb);
    cudaGetSymbolAddress((void**)&Abits,  g_Abits);
    cudaGetSymbolAddress((void**)&H1bits, g_H1bits);

    dim3 blk(256);
    dim3 g512 (NN/128, CC/128,   BB);   // (8, 4, 16)
    dim3 g2048(NN/128, HIDC/128, BB);   // (8, 16, 16)
    int gbC = (int)(((size_t)BB*CC*NN) / 256);   // 32768

    // Q / K / V branches: conv1x1 -> BN stats -> binarize (uint8 for attn)
    gemm128<<<g512, blk>>>(q_w, x, nullptr, Y, CC, CC);
    stats_kernel<<<CC, 256>>>(Y, CC, mean, rstd);
    bin_u8_kernel<<<gbC, 256>>>(Y, mean, rstd, q_g, q_b, Qb, CC);

    gemm128<<<g512, blk>>>(k_w, x, nullptr, Y, CC, CC);
    stats_kernel<<<CC, 256>>>(Y, CC, mean, rstd);
    bin_u8_kernel<<<gbC, 256>>>(Y, mean, rstd, k_g, k_b, Kb, CC);

    gemm128<<<g512, blk>>>(v_w, x, nullptr, Y, CC, CC);
    stats_kernel<<<CC, 256>>>(Y, CC, mean, rstd);
    bin_u8_kernel<<<gbC, 256>>>(Y, mean, rstd, v_g, v_b, Vb, CC);

    // Fused spiking attention via Q(K^T V) -> bit-packed spikes
    attn_kernel<<<BB*HH, 256>>>(Qb, Kb, Vb, Abits);

    // proj: sparse binary GEMM (W^T gather-sum over active channels)
    transpose_w<<<dim3(CC/32, CC/32), 256>>>(proj_w, Wt, CC, CC);
    sparse_gemm<<<BB*NN, 128>>>(Wt, Abits, proj_bias, Y, CC);
    stats_kernel<<<CC, 256>>>(Y, CC, mean, rstd);
    bin_resid_kernel<<<gbC, 256>>>(Y, mean, rstd, proj_g, proj_b, x, X1, CC);

    // fc1: dense GEMM -> BN -> spike (bit-packed)
    gemm128<<<g2048, blk>>>(fc1_w, X1, fc1_bias, Y, HIDC, CC);
    stats_kernel<<<HIDC, 256>>>(Y, HIDC, mean, rstd);
    bin_pack_kernel<<<(BB*(HIDC/32)*32*32)/256, 256>>>(Y, mean, rstd, fc1_g, fc1_b, H1bits);

    // fc2: sparse binary GEMM -> BN -> spike -> residual 2
    transpose_w<<<dim3(HIDC/32, CC/32), 256>>>(fc2_w, Wt, CC, HIDC);
    sparse_gemm<<<BB*NN, 128>>>(Wt, H1bits, fc2_bias, Y, HIDC);
    stats_kernel<<<CC, 256>>>(Y, CC, mean, rstd);
    bin_final_kernel<<<gbC, 256>>>(Y, mean, rstd, fc2_g, fc2_b, X1, out, CC);
}